// round 11
// baseline (speedup 1.0000x reference)
#include <cuda_runtime.h>
#include <cuda_fp16.h>
#include <cstdint>

// DepthAwareConv2d as fp16 mma.sync (m16n8k16, fp32 accum) implicit GEMM.
// R11 = R10 + 2-way K-split (blockIdx.z picks c-groups 0-3 or 4-7, 2048 CTAs)
// to cut wave-quantization tail (4 waves -> 3.5 wave-equivalents). Output is
// zeroed via cudaMemsetAsync (graph-legal memset node); both K-halves
// accumulate with atomicAdd (REDG, no return); kh=0 folds the bias.

#define Nn 4
#define Cc 128
#define Oo 256
#define Hh 128
#define Ww 128
#define CG 16                // channels per group (= MMA K)
#define NCG (Cc / CG)        // 8
#define NCGH (NCG / 2)       // 4 c-groups per K-half
#define RS2 136              // B row stride in b32 units (conflict-free)

// A image per (o-tile 128, c-group): [tap 9][mt 8][lane 32][r 4] b32
#define ASZ 9216
// B image per c-group: 8 cpairs x 3 rows x RS2 b32
#define BSZ (8 * 3 * RS2)    // 3264 b32

// grid split for the merged prep kernel
#define GXD (Nn * (Cc / 2) * Hh * Ww / 4 / 256)   // 4096 blocks
#define GWA ((2 * NCG * ASZ + 255) / 256)         // 576 blocks

__device__ uint32_t g_xdt2[Nn * (Cc / 2) * Hh * Ww];   // half2(xd[2c], xd[2c+1])
__device__ uint32_t g_wta2[2 * NCG * ASZ];             // fragment-major fp16 weights

// ----------------------------- helpers --------------------------------------
__device__ __forceinline__ void cp_async16(uint32_t dst, const void* src) {
    asm volatile("cp.async.cg.shared.global [%0], [%1], 16;"
                 :: "r"(dst), "l"(src) : "memory");
}
__device__ __forceinline__ void cp_async16z(uint32_t dst, const void* src, uint32_t sz) {
    asm volatile("cp.async.cg.shared.global [%0], [%1], 16, %2;"
                 :: "r"(dst), "l"(src), "r"(sz) : "memory");
}
__device__ __forceinline__ void cp_commit() {
    asm volatile("cp.async.commit_group;" ::: "memory");
}
template <int N>
__device__ __forceinline__ void cp_wait() {
    asm volatile("cp.async.wait_group %0;" :: "n"(N) : "memory");
}
__device__ __forceinline__ uint32_t lds32(uint32_t addr) {
    uint32_t v;
    asm volatile("ld.shared.b32 %0, [%1];" : "=r"(v) : "r"(addr));
    return v;
}
__device__ __forceinline__ void mma_f16(float& c0, float& c1, float& c2, float& c3,
                                        uint32_t a0, uint32_t a1, uint32_t a2, uint32_t a3,
                                        uint32_t b0, uint32_t b1) {
    asm("mma.sync.aligned.m16n8k16.row.col.f32.f16.f16.f32 "
        "{%0,%1,%2,%3}, {%4,%5,%6,%7}, {%8,%9}, {%0,%1,%2,%3};"
        : "+f"(c0), "+f"(c1), "+f"(c2), "+f"(c3)
        : "r"(a0), "r"(a1), "r"(a2), "r"(a3), "r"(b0), "r"(b1));
}
__device__ __forceinline__ uint32_t pack_h2(float lo, float hi) {
    __half2 h = __floats2half2_rn(lo, hi);
    return *reinterpret_cast<uint32_t*>(&h);
}

// --------------------------- merged prep kernel ------------------------------
// Blocks [0, GXD): xd pack.  Blocks [GXD, GXD+GWA): weight permute.
__global__ void prep_all_kernel(const float* __restrict__ x,
                                const float* __restrict__ dep,
                                const float* __restrict__ w)
{
    if (blockIdx.x < GXD) {
        const int i = (blockIdx.x * 256 + threadIdx.x) * 4;
        const int n  = i >> 20;
        const int cp = (i >> 14) & 63;
        const int hw = i & 16383;
        const float4 x0 = *reinterpret_cast<const float4*>(x + (((size_t)(n * Cc + 2 * cp)) << 14) + hw);
        const float4 x1 = *reinterpret_cast<const float4*>(x + (((size_t)(n * Cc + 2 * cp + 1)) << 14) + hw);
        const float4 dv = *reinterpret_cast<const float4*>(dep + ((size_t)n << 14) + hw);
        uint4 r;
        r.x = pack_h2(x0.x * dv.x, x1.x * dv.x);
        r.y = pack_h2(x0.y * dv.y, x1.y * dv.y);
        r.z = pack_h2(x0.z * dv.z, x1.z * dv.z);
        r.w = pack_h2(x0.w * dv.w, x1.w * dv.w);
        *reinterpret_cast<uint4*>(g_xdt2 + i) = r;
    } else {
        const int i = (blockIdx.x - GXD) * 256 + threadIdx.x;
        if (i >= 2 * NCG * ASZ) return;
        const int r    = i & 3;
        const int lane = (i >> 2) & 31;
        const int mt   = (i >> 7) & 7;
        const int tap  = (i >> 10) % 9;
        const int rest = i / ASZ;
        const int cg   = rest & (NCG - 1);
        const int ot   = rest >> 3;
        const int o  = ot * 128 + mt * 16 + (r & 1) * 8 + (lane >> 2);
        const int cb = cg * CG + (lane & 3) * 2 + ((r >> 1) << 3);
        g_wta2[i] = pack_h2(w[(o * Cc + cb) * 9 + tap], w[(o * Cc + cb + 1) * 9 + tap]);
    }
}

// ------------------------------- main kernel --------------------------------
// grid (Nn*Hh, 2 ot, 2 kh), 256 threads. CTA: M=128 o, N=128 px (one row),
// K-half = 4 c-groups. Accumulates into pre-zeroed out via atomicAdd (REDG).
__global__ __launch_bounds__(256, 2)
void conv_f16_mma_kernel(const float* __restrict__ bias, float* __restrict__ out)
{
    extern __shared__ uint32_t smem[];
    const uint32_t sAb = (uint32_t)__cvta_generic_to_shared(smem);
    const uint32_t sBb = sAb + 2 * ASZ * 4;

    const int tid   = threadIdx.x;
    const int lane  = tid & 31;
    const int wid   = tid >> 5;
    const int warpM = wid >> 2;                  // 0..1
    const int warpN = wid & 3;                   // 0..3

    const int pix = blockIdx.x * 128;
    const int n   = pix >> 14;
    const int y   = (pix >> 7) & (Hh - 1);
    const int ot  = blockIdx.y;
    const int kh  = blockIdx.z;                  // K-half: c-groups kh*4 .. kh*4+3
    const int oBase = ot * 128;

    const uint32_t* xsrc = g_xdt2 + ((size_t)n << 20);
    const uint32_t* asrc = g_wta2 + (size_t)(ot * NCG + kh * NCGH) * ASZ;

    // prefetch bias early (kh=0 owns the bias contribution)
    const int g = lane >> 2, t = lane & 3;
    float bv[4][2];
    #pragma unroll
    for (int m = 0; m < 4; m++) {
        const int oLo = oBase + warpM * 64 + m * 16 + g;
        bv[m][0] = kh ? 0.0f : bias[oLo];
        bv[m][1] = kh ? 0.0f : bias[oLo + 8];
    }

    // ---- zero halo/filler pads in both B buffers (2 x 24 rows x 8 slots) ----
    for (int idx = tid; idx < 384; idx += 256) {
        const int buf = idx / 192, rem = idx % 192;
        const int row = rem >> 3, p = rem & 7;
        smem[2 * ASZ + buf * BSZ + row * RS2 + (p < 4 ? p : 128 + p)] = 0u;
    }

    // ---- staging: one c-group (local index) into buffer `buf` ----
    auto stage = [&](int cg, int buf) {
        const uint32_t* as = asrc + (size_t)cg * ASZ;
        const uint32_t dA = sAb + buf * (ASZ * 4);
        #pragma unroll
        for (int i = 0; i < 9; i++) {                    // A: 2304 x 16B, linear
            const int idx = i * 256 + tid;
            cp_async16(dA + idx * 16, as + idx * 4);
        }
        const uint32_t dB = sBb + buf * (BSZ * 4);
        const int cgl = kh * NCGH + cg;                  // global c-group
        #pragma unroll
        for (int i = 0; i < 3; i++) {                    // B: 768 x 16B, rows
            const int idx = i * 256 + tid;
            const int pair = idx >> 5, seg = idx & 31;   // pair = cpair*3 + row
            const int cp = pair / 3, rr = pair - cp * 3;
            const int yy = y + rr - 1;
            const bool inb = (unsigned)yy < (unsigned)Hh;
            const int yc = inb ? yy : 0;
            const uint32_t* src = xsrc + (((size_t)(cgl * 8 + cp)) << 14) + (yc << 7) + seg * 4;
            cp_async16z(dB + (pair * RS2 + 4 + seg * 4) * 4, src, inb ? 16u : 0u);
        }
        cp_commit();
    };

    float acc[4][4][4];
    #pragma unroll
    for (int m = 0; m < 4; m++)
        #pragma unroll
        for (int j = 0; j < 4; j++)
            #pragma unroll
            for (int r = 0; r < 4; r++) acc[m][j][r] = 0.0f;

    // per-thread B base: cpair = lane%4, pixel = warpN*32 + lane/4, x shift -1
    const uint32_t bTh = ((lane & 3) * 3 * RS2 + 4 + warpN * 32 + (lane >> 2) - 1) * 4;

    stage(0, 0);

    for (int cg = 0; cg < NCGH; ++cg) {
        const int buf = cg & 1;
        if (cg + 1 < NCGH) { stage(cg + 1, buf ^ 1); cp_wait<1>(); }
        else               { cp_wait<0>(); }
        __syncthreads();

        const uint4* fA = reinterpret_cast<const uint4*>(smem) + buf * (ASZ / 4);
        const uint32_t bBase0 = sBb + buf * (BSZ * 4) + bTh;      // cpair = lane%4
        const uint32_t bBase1 = bBase0 + 4 * 3 * RS2 * 4;         // cpair + 4

        #pragma unroll
        for (int tap = 0; tap < 9; tap++) {
            const int dy = tap / 3, dx = tap - dy * 3;
            const uint32_t doff = (dy * RS2 + dx) * 4;

            uint32_t b0[4], b1[4];
            #pragma unroll
            for (int j = 0; j < 4; j++) {
                b0[j] = lds32(bBase0 + doff + j * 32);   // +8 px per n-subtile
                b1[j] = lds32(bBase1 + doff + j * 32);
            }
            uint4 av[4];
            #pragma unroll
            for (int m = 0; m < 4; m++)
                av[m] = fA[(tap * 8 + warpM * 4 + m) * 32 + lane];

            #pragma unroll
            for (int m = 0; m < 4; m++)
                #pragma unroll
                for (int j = 0; j < 4; j++)
                    mma_f16(acc[m][j][0], acc[m][j][1], acc[m][j][2], acc[m][j][3],
                            av[m].x, av[m].y, av[m].z, av[m].w, b0[j], b1[j]);
        }
        // protect buffer reuse by the NEXT stage; no next stage on last iter
        if (cg + 2 < NCGH) __syncthreads();
    }

    // ---- epilogue: accumulate partial (+bias for kh=0) via REDG ----
    #pragma unroll
    for (int m = 0; m < 4; m++) {
        const int oLo = oBase + warpM * 64 + m * 16 + g;
        const size_t rowLo = (((size_t)(n * Oo + oLo))     << 14) + (y << 7);
        const size_t rowHi = (((size_t)(n * Oo + oLo + 8)) << 14) + (y << 7);
        #pragma unroll
        for (int j = 0; j < 4; j++) {
            const int xb = warpN * 32 + j * 8 + 2 * t;
            atomicAdd(out + rowLo + xb,     acc[m][j][0] + bv[m][0]);
            atomicAdd(out + rowLo + xb + 1, acc[m][j][1] + bv[m][0]);
            atomicAdd(out + rowHi + xb,     acc[m][j][2] + bv[m][1]);
            atomicAdd(out + rowHi + xb + 1, acc[m][j][3] + bv[m][1]);
        }
    }
}

// ------------------------------- launcher -----------------------------------
extern "C" void kernel_launch(void* const* d_in, const int* in_sizes, int n_in,
                              void* d_out, int out_size)
{
    const float* x    = (const float*)d_in[0];
    const float* dep  = (const float*)d_in[1];
    // d_in[2] = camera_params (unused by the math)
    const float* w    = (const float*)d_in[3];
    const float* bias = (const float*)d_in[4];
    float* out = (float*)d_out;

    constexpr int SMEM_BYTES = (2 * ASZ + 2 * BSZ) * 4;   // 99,840 B

    static bool attr_set = false;
    if (!attr_set) {
        cudaFuncSetAttribute(conv_f16_mma_kernel,
                             cudaFuncAttributeMaxDynamicSharedMemorySize, SMEM_BYTES);
        attr_set = true;
    }

    // zero output for REDG accumulation (memset node is graph-capturable)
    cudaMemsetAsync(d_out, 0, (size_t)out_size * sizeof(float));

    prep_all_kernel<<<GXD + GWA, 256>>>(x, dep, w);

    dim3 grid(Nn * Hh, 2, 2);   // 2048 CTAs (K-split x2)
    conv_f16_mma_kernel<<<grid, 256, SMEM_BYTES>>>(bias, out);
}

// round 12
// speedup vs baseline: 1.3096x; 1.3096x over previous
#include <cuda_runtime.h>
#include <cuda_fp16.h>
#include <cstdint>

// DepthAwareConv2d as fp16 mma.sync (m16n8k16, fp32 accum) implicit GEMM.
// R12 = R10 with A (weights) loaded DIRECTLY from global fragment-major layout
// via ld.global.nc.v4 (no SMEM round-trip: weights are shared by all CTAs of an
// ot and stay L1-resident), and a 4-stage B-only cp.async pipeline (depth-3
// prefetch, wait_group 3 with filler commits).

#define Nn 4
#define Cc 128
#define Oo 256
#define Hh 128
#define Ww 128
#define CG 16                // channels per group (= MMA K)
#define NCG (Cc / CG)        // 8
#define RS2 136              // B row stride in b32 units (conflict-free)
#define NST 4                // B pipeline stages

// A image per (o-tile 128, c-group): [tap 9][mt 8][lane 32][r 4] b32
#define ASZ 9216
// B image per c-group: 8 cpairs x 3 rows x RS2 b32
#define BSZ (8 * 3 * RS2)    // 3264 b32

// grid split for the merged prep kernel
#define GXD (Nn * (Cc / 2) * Hh * Ww / 4 / 256)   // 4096 blocks
#define GWA ((2 * NCG * ASZ + 255) / 256)         // 576 blocks

__device__ uint32_t g_xdt2[Nn * (Cc / 2) * Hh * Ww];   // half2(xd[2c], xd[2c+1])
__device__ uint32_t g_wta2[2 * NCG * ASZ];             // fragment-major fp16 weights

// ----------------------------- helpers --------------------------------------
__device__ __forceinline__ void cp_async16z(uint32_t dst, const void* src, uint32_t sz) {
    asm volatile("cp.async.cg.shared.global [%0], [%1], 16, %2;"
                 :: "r"(dst), "l"(src), "r"(sz) : "memory");
}
__device__ __forceinline__ void cp_commit() {
    asm volatile("cp.async.commit_group;" ::: "memory");
}
template <int N>
__device__ __forceinline__ void cp_wait() {
    asm volatile("cp.async.wait_group %0;" :: "n"(N) : "memory");
}
__device__ __forceinline__ uint32_t lds32(uint32_t addr) {
    uint32_t v;
    asm volatile("ld.shared.b32 %0, [%1];" : "=r"(v) : "r"(addr));
    return v;
}
__device__ __forceinline__ void mma_f16(float& c0, float& c1, float& c2, float& c3,
                                        uint32_t a0, uint32_t a1, uint32_t a2, uint32_t a3,
                                        uint32_t b0, uint32_t b1) {
    asm("mma.sync.aligned.m16n8k16.row.col.f32.f16.f16.f32 "
        "{%0,%1,%2,%3}, {%4,%5,%6,%7}, {%8,%9}, {%0,%1,%2,%3};"
        : "+f"(c0), "+f"(c1), "+f"(c2), "+f"(c3)
        : "r"(a0), "r"(a1), "r"(a2), "r"(a3), "r"(b0), "r"(b1));
}
__device__ __forceinline__ uint32_t pack_h2(float lo, float hi) {
    __half2 h = __floats2half2_rn(lo, hi);
    return *reinterpret_cast<uint32_t*>(&h);
}

// --------------------------- merged prep kernel ------------------------------
// Blocks [0, GXD): xd pack.  Blocks [GXD, GXD+GWA): weight permute.
__global__ void prep_all_kernel(const float* __restrict__ x,
                                const float* __restrict__ dep,
                                const float* __restrict__ w)
{
    if (blockIdx.x < GXD) {
        const int i = (blockIdx.x * 256 + threadIdx.x) * 4;
        const int n  = i >> 20;
        const int cp = (i >> 14) & 63;
        const int hw = i & 16383;
        const float4 x0 = *reinterpret_cast<const float4*>(x + (((size_t)(n * Cc + 2 * cp)) << 14) + hw);
        const float4 x1 = *reinterpret_cast<const float4*>(x + (((size_t)(n * Cc + 2 * cp + 1)) << 14) + hw);
        const float4 dv = *reinterpret_cast<const float4*>(dep + ((size_t)n << 14) + hw);
        uint4 r;
        r.x = pack_h2(x0.x * dv.x, x1.x * dv.x);
        r.y = pack_h2(x0.y * dv.y, x1.y * dv.y);
        r.z = pack_h2(x0.z * dv.z, x1.z * dv.z);
        r.w = pack_h2(x0.w * dv.w, x1.w * dv.w);
        *reinterpret_cast<uint4*>(g_xdt2 + i) = r;
    } else {
        const int i = (blockIdx.x - GXD) * 256 + threadIdx.x;
        if (i >= 2 * NCG * ASZ) return;
        const int r    = i & 3;
        const int lane = (i >> 2) & 31;
        const int mt   = (i >> 7) & 7;
        const int tap  = (i >> 10) % 9;
        const int rest = i / ASZ;
        const int cg   = rest & (NCG - 1);
        const int ot   = rest >> 3;
        const int o  = ot * 128 + mt * 16 + (r & 1) * 8 + (lane >> 2);
        const int cb = cg * CG + (lane & 3) * 2 + ((r >> 1) << 3);
        g_wta2[i] = pack_h2(w[(o * Cc + cb) * 9 + tap], w[(o * Cc + cb + 1) * 9 + tap]);
    }
}

// ------------------------------- main kernel --------------------------------
// grid (Nn*Hh, 2), 256 threads. CTA: M=128 o, N=128 px (one image row), all K.
// SMEM: B-only, NST=4 stages of BSZ b32. B row: data x at b32 [4..131],
// halo x=-1 at [3], x=128 at [132]; filler [0..2],[133..135] zeroed once.
// A fragments come straight from g_wta2 via ld.global.nc.v4.
__global__ __launch_bounds__(256, 2)
void conv_f16_mma_kernel(const float* __restrict__ bias, float* __restrict__ out)
{
    extern __shared__ uint32_t smem[];
    const uint32_t sBb = (uint32_t)__cvta_generic_to_shared(smem);

    const int tid   = threadIdx.x;
    const int lane  = tid & 31;
    const int wid   = tid >> 5;
    const int warpM = wid >> 2;                  // 0..1
    const int warpN = wid & 3;                   // 0..3

    const int pix = blockIdx.x * 128;
    const int n   = pix >> 14;
    const int y   = (pix >> 7) & (Hh - 1);
    const int ot  = blockIdx.y;
    const int oBase = ot * 128;

    const uint32_t* xsrc = g_xdt2 + ((size_t)n << 20);
    const uint4*    aV   = reinterpret_cast<const uint4*>(g_wta2 + (size_t)(ot * NCG) * ASZ);

    // ---- zero halo/filler pads in all B stages (NST x 24 rows x 8 slots) ----
    for (int idx = tid; idx < NST * 192; idx += 256) {
        const int buf = idx / 192, rem = idx % 192;
        const int row = rem >> 3, p = rem & 7;
        smem[buf * BSZ + row * RS2 + (p < 4 ? p : 128 + p)] = 0u;
    }

    // ---- B staging: one c-group into stage `buf` (16B cp.async.cg) ----
    auto stageB = [&](int cg, int buf) {
        const uint32_t dB = sBb + buf * (BSZ * 4);
        #pragma unroll
        for (int i = 0; i < 3; i++) {                    // 768 x 16B
            const int idx = i * 256 + tid;
            const int pair = idx >> 5, seg = idx & 31;   // pair = cpair*3 + row
            const int cp = pair / 3, rr = pair - cp * 3;
            const int yy = y + rr - 1;
            const bool inb = (unsigned)yy < (unsigned)Hh;
            const int yc = inb ? yy : 0;
            const uint32_t* src = xsrc + (((size_t)(cg * 8 + cp)) << 14) + (yc << 7) + seg * 4;
            cp_async16z(dB + (pair * RS2 + 4 + seg * 4) * 4, src, inb ? 16u : 0u);
        }
        cp_commit();
    };

    float acc[4][4][4];
    #pragma unroll
    for (int m = 0; m < 4; m++)
        #pragma unroll
        for (int j = 0; j < 4; j++)
            #pragma unroll
            for (int r = 0; r < 4; r++) acc[m][j][r] = 0.0f;

    // per-thread B base: cpair = lane%4, pixel = warpN*32 + lane/4, x shift -1
    const uint32_t bTh = ((lane & 3) * 3 * RS2 + 4 + warpN * 32 + (lane >> 2) - 1) * 4;

    stageB(0, 0);
    stageB(1, 1);
    stageB(2, 2);

    for (int cg = 0; cg < NCG; ++cg) {
        const int buf = cg & (NST - 1);

        // all warps past compute(cg-1) (which read the buffer stage(cg+3) writes)
        __syncthreads();
        if (cg + 3 < NCG) stageB(cg + 3, (cg + 3) & (NST - 1));
        else              cp_commit();                   // filler keeps group count
        cp_wait<3>();                                    // stage(cg) complete (own)
        __syncthreads();                                 // ... and visible to all

        const uint32_t bBase0 = sBb + buf * (BSZ * 4) + bTh;      // cpair = lane%4
        const uint32_t bBase1 = bBase0 + 4 * 3 * RS2 * 4;         // cpair + 4
        const uint4* aCg = aV + (size_t)cg * (ASZ / 4);

        #pragma unroll
        for (int tap = 0; tap < 9; tap++) {
            const int dy = tap / 3, dx = tap - dy * 3;
            const uint32_t doff = (dy * RS2 + dx) * 4;

            uint32_t b0[4], b1[4];
            #pragma unroll
            for (int j = 0; j < 4; j++) {
                b0[j] = lds32(bBase0 + doff + j * 32);   // +8 px per n-subtile
                b1[j] = lds32(bBase1 + doff + j * 32);
            }
            uint4 av[4];
            #pragma unroll
            for (int m = 0; m < 4; m++)
                av[m] = __ldg(aCg + (tap * 8 + warpM * 4 + m) * 32 + lane);

            #pragma unroll
            for (int m = 0; m < 4; m++)
                #pragma unroll
                for (int j = 0; j < 4; j++)
                    mma_f16(acc[m][j][0], acc[m][j][1], acc[m][j][2], acc[m][j][3],
                            av[m].x, av[m].y, av[m].z, av[m].w, b0[j], b1[j]);
        }
    }

    // ---- epilogue: +bias, direct STG.64 ----
    const int g = lane >> 2, t = lane & 3;
    #pragma unroll
    for (int m = 0; m < 4; m++) {
        const int oLo = oBase + warpM * 64 + m * 16 + g;
        const float bLo = bias[oLo], bHi = bias[oLo + 8];
        const size_t rowLo = (((size_t)(n * Oo + oLo))     << 14) + (y << 7);
        const size_t rowHi = (((size_t)(n * Oo + oLo + 8)) << 14) + (y << 7);
        #pragma unroll
        for (int j = 0; j < 4; j++) {
            const int xb = warpN * 32 + j * 8 + 2 * t;
            float2 lo = make_float2(acc[m][j][0] + bLo, acc[m][j][1] + bLo);
            float2 hi = make_float2(acc[m][j][2] + bHi, acc[m][j][3] + bHi);
            *reinterpret_cast<float2*>(out + rowLo + xb) = lo;
            *reinterpret_cast<float2*>(out + rowHi + xb) = hi;
        }
    }
}

// ------------------------------- launcher -----------------------------------
extern "C" void kernel_launch(void* const* d_in, const int* in_sizes, int n_in,
                              void* d_out, int out_size)
{
    const float* x    = (const float*)d_in[0];
    const float* dep  = (const float*)d_in[1];
    // d_in[2] = camera_params (unused by the math)
    const float* w    = (const float*)d_in[3];
    const float* bias = (const float*)d_in[4];
    float* out = (float*)d_out;

    constexpr int SMEM_BYTES = NST * BSZ * 4;   // 52,224 B

    static bool attr_set = false;
    if (!attr_set) {
        cudaFuncSetAttribute(conv_f16_mma_kernel,
                             cudaFuncAttributeMaxDynamicSharedMemorySize, SMEM_BYTES);
        attr_set = true;
    }

    prep_all_kernel<<<GXD + GWA, 256>>>(x, dep, w);

    dim3 grid(Nn * Hh, 2, 1);   // 1024 CTAs
    conv_f16_mma_kernel<<<grid, 256, SMEM_BYTES>>>(bias, out);
}

// round 13
// speedup vs baseline: 1.3815x; 1.0549x over previous
#include <cuda_runtime.h>
#include <cuda_fp16.h>
#include <cstdint>

// DepthAwareConv2d as fp16 mma.sync (m16n8k16, fp32 accum) implicit GEMM.
// R13 = R12 (A direct from global fragment-major; B via cp.async) with the
// FULL K staged up front: 8 B-stages (104.4 KB, still 2 CTA/SM), loop is just
// wait_group(7-cg) -> one __syncthreads -> compute. No in-loop staging, no
// buffer reuse, half the barriers.

#define Nn 4
#define Cc 128
#define Oo 256
#define Hh 128
#define Ww 128
#define CG 16                // channels per group (= MMA K)
#define NCG (Cc / CG)        // 8
#define RS2 136              // B row stride in b32 units (conflict-free)

// A image per (o-tile 128, c-group): [tap 9][mt 8][lane 32][r 4] b32
#define ASZ 9216
// B image per c-group: 8 cpairs x 3 rows x RS2 b32
#define BSZ (8 * 3 * RS2)    // 3264 b32

// grid split for the merged prep kernel
#define GXD (Nn * (Cc / 2) * Hh * Ww / 4 / 256)   // 4096 blocks
#define GWA ((2 * NCG * ASZ + 255) / 256)         // 576 blocks

__device__ uint32_t g_xdt2[Nn * (Cc / 2) * Hh * Ww];   // half2(xd[2c], xd[2c+1])
__device__ uint32_t g_wta2[2 * NCG * ASZ];             // fragment-major fp16 weights

// ----------------------------- helpers --------------------------------------
__device__ __forceinline__ void cp_async16z(uint32_t dst, const void* src, uint32_t sz) {
    asm volatile("cp.async.cg.shared.global [%0], [%1], 16, %2;"
                 :: "r"(dst), "l"(src), "r"(sz) : "memory");
}
__device__ __forceinline__ void cp_commit() {
    asm volatile("cp.async.commit_group;" ::: "memory");
}
template <int N>
__device__ __forceinline__ void cp_wait() {
    asm volatile("cp.async.wait_group %0;" :: "n"(N) : "memory");
}
// constant-foldable under #pragma unroll
__device__ __forceinline__ void cp_wait_n(int n) {
    switch (n) {
        case 0: cp_wait<0>(); break;
        case 1: cp_wait<1>(); break;
        case 2: cp_wait<2>(); break;
        case 3: cp_wait<3>(); break;
        case 4: cp_wait<4>(); break;
        case 5: cp_wait<5>(); break;
        case 6: cp_wait<6>(); break;
        default: cp_wait<7>(); break;
    }
}
__device__ __forceinline__ uint32_t lds32(uint32_t addr) {
    uint32_t v;
    asm volatile("ld.shared.b32 %0, [%1];" : "=r"(v) : "r"(addr));
    return v;
}
__device__ __forceinline__ void mma_f16(float& c0, float& c1, float& c2, float& c3,
                                        uint32_t a0, uint32_t a1, uint32_t a2, uint32_t a3,
                                        uint32_t b0, uint32_t b1) {
    asm("mma.sync.aligned.m16n8k16.row.col.f32.f16.f16.f32 "
        "{%0,%1,%2,%3}, {%4,%5,%6,%7}, {%8,%9}, {%0,%1,%2,%3};"
        : "+f"(c0), "+f"(c1), "+f"(c2), "+f"(c3)
        : "r"(a0), "r"(a1), "r"(a2), "r"(a3), "r"(b0), "r"(b1));
}
__device__ __forceinline__ uint32_t pack_h2(float lo, float hi) {
    __half2 h = __floats2half2_rn(lo, hi);
    return *reinterpret_cast<uint32_t*>(&h);
}

// --------------------------- merged prep kernel ------------------------------
// Blocks [0, GXD): xd pack.  Blocks [GXD, GXD+GWA): weight permute.
__global__ void prep_all_kernel(const float* __restrict__ x,
                                const float* __restrict__ dep,
                                const float* __restrict__ w)
{
    if (blockIdx.x < GXD) {
        const int i = (blockIdx.x * 256 + threadIdx.x) * 4;
        const int n  = i >> 20;
        const int cp = (i >> 14) & 63;
        const int hw = i & 16383;
        const float4 x0 = *reinterpret_cast<const float4*>(x + (((size_t)(n * Cc + 2 * cp)) << 14) + hw);
        const float4 x1 = *reinterpret_cast<const float4*>(x + (((size_t)(n * Cc + 2 * cp + 1)) << 14) + hw);
        const float4 dv = *reinterpret_cast<const float4*>(dep + ((size_t)n << 14) + hw);
        uint4 r;
        r.x = pack_h2(x0.x * dv.x, x1.x * dv.x);
        r.y = pack_h2(x0.y * dv.y, x1.y * dv.y);
        r.z = pack_h2(x0.z * dv.z, x1.z * dv.z);
        r.w = pack_h2(x0.w * dv.w, x1.w * dv.w);
        *reinterpret_cast<uint4*>(g_xdt2 + i) = r;
    } else {
        const int i = (blockIdx.x - GXD) * 256 + threadIdx.x;
        if (i >= 2 * NCG * ASZ) return;
        const int r    = i & 3;
        const int lane = (i >> 2) & 31;
        const int mt   = (i >> 7) & 7;
        const int tap  = (i >> 10) % 9;
        const int rest = i / ASZ;
        const int cg   = rest & (NCG - 1);
        const int ot   = rest >> 3;
        const int o  = ot * 128 + mt * 16 + (r & 1) * 8 + (lane >> 2);
        const int cb = cg * CG + (lane & 3) * 2 + ((r >> 1) << 3);
        g_wta2[i] = pack_h2(w[(o * Cc + cb) * 9 + tap], w[(o * Cc + cb + 1) * 9 + tap]);
    }
}

// ------------------------------- main kernel --------------------------------
// grid (Nn*Hh, 2), 256 threads. CTA: M=128 o, N=128 px (one image row), all K.
// SMEM: B-only, NCG=8 stages of BSZ b32 (each written exactly once).
// B row: data x at b32 [4..131], halo x=-1 at [3], x=128 at [132];
// filler [0..2],[133..135] zeroed once. A direct via ld.global.nc.v4.
__global__ __launch_bounds__(256, 2)
void conv_f16_mma_kernel(const float* __restrict__ bias, float* __restrict__ out)
{
    extern __shared__ uint32_t smem[];
    const uint32_t sBb = (uint32_t)__cvta_generic_to_shared(smem);

    const int tid   = threadIdx.x;
    const int lane  = tid & 31;
    const int wid   = tid >> 5;
    const int warpM = wid >> 2;                  // 0..1
    const int warpN = wid & 3;                   // 0..3

    const int pix = blockIdx.x * 128;
    const int n   = pix >> 14;
    const int y   = (pix >> 7) & (Hh - 1);
    const int ot  = blockIdx.y;
    const int oBase = ot * 128;

    const uint32_t* xsrc = g_xdt2 + ((size_t)n << 20);
    const uint4*    aV   = reinterpret_cast<const uint4*>(g_wta2 + (size_t)(ot * NCG) * ASZ);

    // ---- zero halo/filler pads in all 8 B stages (8 x 24 rows x 8 slots) ----
    for (int idx = tid; idx < NCG * 192; idx += 256) {
        const int buf = idx / 192, rem = idx % 192;
        const int row = rem >> 3, p = rem & 7;
        smem[buf * BSZ + row * RS2 + (p < 4 ? p : 128 + p)] = 0u;
    }

    // ---- stage ALL 8 c-groups up front (8 commit groups, deep MLP) ----
    #pragma unroll
    for (int cg = 0; cg < NCG; ++cg) {
        const uint32_t dB = sBb + cg * (BSZ * 4);
        #pragma unroll
        for (int i = 0; i < 3; i++) {                    // 768 x 16B per group
            const int idx = i * 256 + tid;
            const int pair = idx >> 5, seg = idx & 31;   // pair = cpair*3 + row
            const int cp = pair / 3, rr = pair - cp * 3;
            const int yy = y + rr - 1;
            const bool inb = (unsigned)yy < (unsigned)Hh;
            const int yc = inb ? yy : 0;
            const uint32_t* src = xsrc + (((size_t)(cg * 8 + cp)) << 14) + (yc << 7) + seg * 4;
            cp_async16z(dB + (pair * RS2 + 4 + seg * 4) * 4, src, inb ? 16u : 0u);
        }
        cp_commit();
    }

    float acc[4][4][4];
    #pragma unroll
    for (int m = 0; m < 4; m++)
        #pragma unroll
        for (int j = 0; j < 4; j++)
            #pragma unroll
            for (int r = 0; r < 4; r++) acc[m][j][r] = 0.0f;

    // per-thread B base: cpair = lane%4, pixel = warpN*32 + lane/4, x shift -1
    const uint32_t bTh = ((lane & 3) * 3 * RS2 + 4 + warpN * 32 + (lane >> 2) - 1) * 4;

    #pragma unroll
    for (int cg = 0; cg < NCG; ++cg) {
        cp_wait_n(NCG - 1 - cg);      // own copies of stage cg complete
        __syncthreads();              // ... and everyone's, published

        const uint32_t bBase0 = sBb + cg * (BSZ * 4) + bTh;       // cpair = lane%4
        const uint32_t bBase1 = bBase0 + 4 * 3 * RS2 * 4;         // cpair + 4
        const uint4* aCg = aV + (size_t)cg * (ASZ / 4);

        #pragma unroll
        for (int tap = 0; tap < 9; tap++) {
            const int dy = tap / 3, dx = tap - dy * 3;
            const uint32_t doff = (dy * RS2 + dx) * 4;

            uint32_t b0[4], b1[4];
            #pragma unroll
            for (int j = 0; j < 4; j++) {
                b0[j] = lds32(bBase0 + doff + j * 32);   // +8 px per n-subtile
                b1[j] = lds32(bBase1 + doff + j * 32);
            }
            uint4 av[4];
            #pragma unroll
            for (int m = 0; m < 4; m++)
                av[m] = __ldg(aCg + (tap * 8 + warpM * 4 + m) * 32 + lane);

            #pragma unroll
            for (int m = 0; m < 4; m++)
                #pragma unroll
                for (int j = 0; j < 4; j++)
                    mma_f16(acc[m][j][0], acc[m][j][1], acc[m][j][2], acc[m][j][3],
                            av[m].x, av[m].y, av[m].z, av[m].w, b0[j], b1[j]);
        }
    }

    // ---- epilogue: +bias, direct STG.64 ----
    const int g = lane >> 2, t = lane & 3;
    #pragma unroll
    for (int m = 0; m < 4; m++) {
        const int oLo = oBase + warpM * 64 + m * 16 + g;
        const float bLo = bias[oLo], bHi = bias[oLo + 8];
        const size_t rowLo = (((size_t)(n * Oo + oLo))     << 14) + (y << 7);
        const size_t rowHi = (((size_t)(n * Oo + oLo + 8)) << 14) + (y << 7);
        #pragma unroll
        for (int j = 0; j < 4; j++) {
            const int xb = warpN * 32 + j * 8 + 2 * t;
            float2 lo = make_float2(acc[m][j][0] + bLo, acc[m][j][1] + bLo);
            float2 hi = make_float2(acc[m][j][2] + bHi, acc[m][j][3] + bHi);
            *reinterpret_cast<float2*>(out + rowLo + xb) = lo;
            *reinterpret_cast<float2*>(out + rowHi + xb) = hi;
        }
    }
}

// ------------------------------- launcher -----------------------------------
extern "C" void kernel_launch(void* const* d_in, const int* in_sizes, int n_in,
                              void* d_out, int out_size)
{
    const float* x    = (const float*)d_in[0];
    const float* dep  = (const float*)d_in[1];
    // d_in[2] = camera_params (unused by the math)
    const float* w    = (const float*)d_in[3];
    const float* bias = (const float*)d_in[4];
    float* out = (float*)d_out;

    constexpr int SMEM_BYTES = NCG * BSZ * 4;   // 104,448 B

    static bool attr_set = false;
    if (!attr_set) {
        cudaFuncSetAttribute(conv_f16_mma_kernel,
                             cudaFuncAttributeMaxDynamicSharedMemorySize, SMEM_BYTES);
        attr_set = true;
    }

    prep_all_kernel<<<GXD + GWA, 256>>>(x, dep, w);

    dim3 grid(Nn * Hh, 2, 1);   // 1024 CTAs
    conv_f16_mma_kernel<<<grid, 256, SMEM_BYTES>>>(bias, out);
}